// round 10
// baseline (speedup 1.0000x reference)
#include <cuda_runtime.h>
#include <cuda_bf16.h>
#include <math.h>
#include <stdint.h>

// Problem constants
#define N_   256
#define T_   128
#define D_   512
#define H_   1024
#define KTOT 1536          // D + H  (x | h concat; attention folded into PA)
#define G4   4096          // 4*H gate columns

// GEMM tiling: CTA 128(M) x 64(N), K chunks of 64
#define BM_  128
#define BN_  64
#define KC   64
#define STAGES 4
#define STAGE_A 16384      // 128 rows * 128B
#define STAGE_B 8192       // 64 rows * 128B
#define STAGE_BYTES (STAGE_A + STAGE_B)
#define SW_OFF   98304     // w16 stage: 128 rows * 16 * 4B = 8KB
#define GEMM_SMEM (SW_OFF + 8192)          // 106496
#define PAC_OFF  36864     // PAc smem [128][68] fp32 (after Csm [128][68])

// ---------------- persistent device scratch ----------------
__device__ __nv_bfloat16 g_xh[N_ * T_ * D_];          // x splits  [n][t][d]
__device__ __nv_bfloat16 g_xl[N_ * T_ * D_];
__device__ __nv_bfloat16 g_wh[(size_t)G4 * KTOT];     // [col][k] gate-interleaved [Wx;Wh]
__device__ __nv_bfloat16 g_wl[(size_t)G4 * KTOT];
__device__ __nv_bfloat16 g_wah[(size_t)G4 * H_];      // Wattn gate-interleaved [col][k]
__device__ __nv_bfloat16 g_wal[(size_t)G4 * H_];
__device__ __nv_bfloat16 g_ath[4096 * H_];            // A^T splits: row = n*16+p, k = h
__device__ __nv_bfloat16 g_atl[4096 * H_];
__device__ __nv_bfloat16 g_hh[N_ * H_];               // h splits
__device__ __nv_bfloat16 g_hl[N_ * H_];
__device__ float g_PA[(size_t)4096 * G4];             // [(n*16+p)][jg]  67MB fp32, coalesced
__device__ float g_w16[N_ * 16];                      // softmax attention weights
__device__ float g_h[N_ * H_];
__device__ float g_c[N_ * H_];
__device__ float g_b4[G4];                            // [j][gate]

// ---------------- helpers ----------------
__device__ __forceinline__ uint32_t smem_u32(const void* p) {
    uint32_t a;
    asm("{ .reg .u64 t; cvta.to.shared.u64 t, %1; cvt.u32.u64 %0, t; }" : "=r"(a) : "l"(p));
    return a;
}
__device__ __forceinline__ void cp_async16(uint32_t dst, const void* src) {
    asm volatile("cp.async.cg.shared.global [%0], [%1], 16;" :: "r"(dst), "l"(src));
}
#define CP_COMMIT() asm volatile("cp.async.commit_group;" ::: "memory")
#define CP_WAIT2()  asm volatile("cp.async.wait_group 2;" ::: "memory")

__device__ __forceinline__ void ldsm4(uint32_t& r0, uint32_t& r1, uint32_t& r2, uint32_t& r3,
                                      uint32_t addr) {
    asm volatile("ldmatrix.sync.aligned.m8n8.x4.shared.b16 {%0,%1,%2,%3}, [%4];"
                 : "=r"(r0), "=r"(r1), "=r"(r2), "=r"(r3) : "r"(addr));
}
__device__ __forceinline__ void mma16816(float* c, const uint32_t* a, const uint32_t* b) {
    asm volatile("mma.sync.aligned.m16n8k16.row.col.f32.bf16.bf16.f32 "
                 "{%0,%1,%2,%3}, {%4,%5,%6,%7}, {%8,%9}, {%0,%1,%2,%3};"
                 : "+f"(c[0]), "+f"(c[1]), "+f"(c[2]), "+f"(c[3])
                 : "r"(a[0]), "r"(a[1]), "r"(a[2]), "r"(a[3]), "r"(b[0]), "r"(b[1]));
}
__device__ __forceinline__ float sigmoidf_(float x) { return 1.0f / (1.0f + expf(-x)); }
__device__ __forceinline__ void split_bf16(float v, __nv_bfloat16& hi, __nv_bfloat16& lo) {
    hi = __float2bfloat16_rn(v);
    lo = __float2bfloat16_rn(v - __bfloat162float(hi));
}

// ---------------- prep kernels ----------------
__global__ void __launch_bounds__(256) split_x_kernel(const float* __restrict__ x) {
    int idx = blockIdx.x * 256 + threadIdx.x;
    if (idx >= N_ * T_ * D_) return;
    __nv_bfloat16 hi, lo;
    split_bf16(x[idx], hi, lo);
    g_xh[idx] = hi;
    g_xl[idx] = lo;
}

// [Wx;Wh] -> gate-interleaved transposed [col][k], col = j*4+g
__global__ void __launch_bounds__(256) split_w_kernel(
    const float* __restrict__ Wx, const float* __restrict__ Wh) {
    size_t idx = (size_t)blockIdx.x * 256 + threadIdx.x;
    if (idx >= (size_t)G4 * KTOT) return;
    int col = (int)(idx / KTOT);
    int k   = (int)(idx % KTOT);
    int j = col >> 2, g = col & 3;
    float v = (k < D_) ? Wx[(size_t)k * G4 + g * H_ + j]
                       : Wh[(size_t)(k - D_) * G4 + g * H_ + j];
    __nv_bfloat16 hi, lo;
    split_bf16(v, hi, lo);
    g_wh[idx] = hi;
    g_wl[idx] = lo;
}

__global__ void __launch_bounds__(256) split_wattn_kernel(const float* __restrict__ Wattn) {
    size_t idx = (size_t)blockIdx.x * 256 + threadIdx.x;
    if (idx >= (size_t)G4 * H_) return;
    int col = (int)(idx / H_);
    int k   = (int)(idx % H_);
    int j = col >> 2, g = col & 3;
    float v = Wattn[(size_t)k * G4 + g * H_ + j];
    __nv_bfloat16 hi, lo;
    split_bf16(v, hi, lo);
    g_wah[idx] = hi;
    g_wal[idx] = lo;
}

// A[n][h][p] -> At[(n*16+p)][h] bf16 splits
__global__ void __launch_bounds__(256) split_at_kernel(const float* __restrict__ A) {
    int idx = blockIdx.x * 256 + threadIdx.x;    // idx = r*1024 + h
    if (idx >= 4096 * H_) return;
    int r = idx >> 10, h = idx & 1023;
    int n = r >> 4, p = r & 15;
    float v = A[((size_t)n * H_ + h) * 16 + p];
    __nv_bfloat16 hi, lo;
    split_bf16(v, hi, lo);
    g_ath[idx] = hi;
    g_atl[idx] = lo;
}

__global__ void prep_b_kernel(const float* __restrict__ b) {
    int idx = blockIdx.x * 256 + threadIdx.x;    // idx = j*4+g
    if (idx >= G4) return;
    g_b4[idx] = b[(idx & 3) * H_ + (idx >> 2)];
}

__global__ void __launch_bounds__(256) init_kernel(const float* __restrict__ A) {
    int idx = blockIdx.x * 256 + threadIdx.x;    // idx = n*H + h
    if (idx >= N_ * H_) return;
    const float4* ap = (const float4*)(A + (size_t)idx * 16);
    float4 a0 = ap[0], a1 = ap[1], a2 = ap[2], a3 = ap[3];
    float s = a0.x + a0.y + a0.z + a0.w + a1.x + a1.y + a1.z + a1.w +
              a2.x + a2.y + a2.z + a2.w + a3.x + a3.y + a3.z + a3.w;
    float m = s * (1.0f / 16.0f);
    g_h[idx] = m;
    g_c[idx] = m;
    __nv_bfloat16 hi, lo;
    split_bf16(m, hi, lo);
    g_hh[idx] = hi;
    g_hl[idx] = lo;
}

// ---------------- per-step attention scores + softmax (tiny) ----------------
__global__ void __launch_bounds__(256) score_kernel(const float* __restrict__ A) {
    __shared__ float sred[8][16];
    int n = blockIdx.x, tid = threadIdx.x;
    const float* Ab = A + (size_t)n * H_ * 16;
    const float* hb = g_h + (size_t)n * H_;

    float s[16];
#pragma unroll
    for (int p = 0; p < 16; p++) s[p] = 0.0f;
#pragma unroll
    for (int rr = 0; rr < 4; rr++) {
        int row = tid + rr * 256;
        const float4* ap = (const float4*)(Ab + (size_t)row * 16);
        float4 a0 = ap[0], a1 = ap[1], a2 = ap[2], a3 = ap[3];
        float hv = hb[row];
        s[0]  += hv * a0.x; s[1]  += hv * a0.y; s[2]  += hv * a0.z; s[3]  += hv * a0.w;
        s[4]  += hv * a1.x; s[5]  += hv * a1.y; s[6]  += hv * a1.z; s[7]  += hv * a1.w;
        s[8]  += hv * a2.x; s[9]  += hv * a2.y; s[10] += hv * a2.z; s[11] += hv * a2.w;
        s[12] += hv * a3.x; s[13] += hv * a3.y; s[14] += hv * a3.z; s[15] += hv * a3.w;
    }
#pragma unroll
    for (int p = 0; p < 16; p++) {
#pragma unroll
        for (int off = 16; off > 0; off >>= 1)
            s[p] += __shfl_down_sync(0xFFFFFFFF, s[p], off);
    }
    int lane = tid & 31, w = tid >> 5;
    if (lane == 0) {
#pragma unroll
        for (int p = 0; p < 16; p++) sred[w][p] = s[p];
    }
    __syncthreads();
    if (tid == 0) {
        float sc[16], mx = -1e30f;
#pragma unroll
        for (int p = 0; p < 16; p++) {
            float t = 0.0f;
#pragma unroll
            for (int ww = 0; ww < 8; ww++) t += sred[ww][p];
            sc[p] = t * (1.0f / 32.0f);          // / sqrt(H)
            mx = fmaxf(mx, sc[p]);
        }
        float se = 0.0f;
#pragma unroll
        for (int p = 0; p < 16; p++) { sc[p] = expf(sc[p] - mx); se += sc[p]; }
        float inv = 1.0f / se;
#pragma unroll
        for (int p = 0; p < 16; p++) g_w16[n * 16 + p] = sc[p] * inv;
    }
}

// ---------------- 3-pass split-bf16 GEMM (mma.sync), 2 modes ----------------
// MODE 0: PA precompute  PA[r=(n*16+p)][jg] = At[r,:] . Wattn_gi[jg,:]  (K=1024)
// MODE 1: recurrent step C[n][jg] = [x_t|h][n,:] . [Wx;Wh]_gi[jg,:]    (K=1536)
//         + PAc[n][jg] = sum_p w16[n,p]*PA[(n*16+p)][jg] streamed into the
//           mainloop (coalesced float2 per warp, reg accumulators)
//         + epilogue: C + PAc + bias -> LSTM gates -> c,h,out
// grid: (G4/BN_, Mtiles). 256 threads, warps 4(M) x 2(N), warp tile 32x32.
template <int MODE>
__global__ void __launch_bounds__(256, 1) gemm3_kernel(float* __restrict__ out, int t) {
    constexpr int SEGC   = (MODE == 0) ? (H_ / KC) : (KTOT / KC);   // 16 : 24
    constexpr int NCHUNK = 3 * SEGC;                                 // 48 : 72

    extern __shared__ char smem[];
    uint32_t sb = smem_u32(smem);
    const int tid = threadIdx.x;
    const int rowBase = blockIdx.y * BM_;
    const int colBase = blockIdx.x * BN_;
    const int w = tid >> 5, lane = tid & 31;
    const int wm = w & 3, wn = w >> 2;

    float c[2][4][4];
#pragma unroll
    for (int mi = 0; mi < 2; mi++)
#pragma unroll
        for (int ni = 0; ni < 4; ni++)
#pragma unroll
            for (int q = 0; q < 4; q++) c[mi][ni][q] = 0.0f;

    // PAc accumulators: warp w owns n-locals {w, w+8, ..., w+120}; lane -> cols 2*lane,+1
    float2 accPA[16];
    float* sW = (float*)(smem + SW_OFF);
    if constexpr (MODE == 1) {
#pragma unroll
        for (int i = 0; i < 16; i++) accPA[i] = make_float2(0.0f, 0.0f);
        // stage w16 for this CTA's 128 rows into smem (2048 floats)
        {
            const float4* src = (const float4*)(g_w16 + rowBase * 16);
            float4* dst = (float4*)sW;
            dst[tid]       = src[tid];
            dst[tid + 256] = src[tid + 256];
        }
    }

    auto load_stage = [&](int ch) {
        int s = ch & 3;
        int seg = ch / SEGC;                 // 0: Ah*Bh, 1: Al*Bh, 2: Ah*Bl
        int kp = (ch % SEGC) * KC;
        uint32_t sa  = sb + s * STAGE_BYTES;
        uint32_t sbb = sa + STAGE_A;
#pragma unroll
        for (int i = 0; i < 4; i++) {
            int o = tid + i * 256;
            int r = o >> 3, kc = o & 7;
            int k = kp + kc * 8;
            const __nv_bfloat16* src;
            if constexpr (MODE == 0) {
                const __nv_bfloat16* ab = (seg == 1) ? g_atl : g_ath;
                src = ab + (size_t)(rowBase + r) * H_ + k;
            } else {
                if (k < D_) {
                    const __nv_bfloat16* xp = (seg == 1) ? g_xl : g_xh;
                    src = xp + ((size_t)(rowBase + r) * T_ + t) * D_ + k;
                } else {
                    const __nv_bfloat16* hp = (seg == 1) ? g_hl : g_hh;
                    src = hp + (size_t)(rowBase + r) * H_ + (k - D_);
                }
            }
            cp_async16(sa + r * 128 + ((kc ^ (r & 7)) << 4), src);
        }
#pragma unroll
        for (int i = 0; i < 2; i++) {
            int o = tid + i * 256;
            int r = o >> 3, kc = o & 7;
            const __nv_bfloat16* src;
            if constexpr (MODE == 0) {
                const __nv_bfloat16* wb = (seg == 2) ? g_wal : g_wah;
                src = wb + (size_t)(colBase + r) * H_ + kp + kc * 8;
            } else {
                const __nv_bfloat16* wb = (seg == 2) ? g_wl : g_wh;
                src = wb + (size_t)(colBase + r) * KTOT + kp + kc * 8;
            }
            cp_async16(sbb + r * 128 + ((kc ^ (r & 7)) << 4), src);
        }
    };

    load_stage(0); CP_COMMIT();
    load_stage(1); CP_COMMIT();
    load_stage(2); CP_COMMIT();

    const int a_r    = (lane & 15);
    const int a_ksel = (lane >> 4);
    const int b_n    = (lane & 7) + ((lane >> 4) << 3);
    const int b_ksel = (lane >> 3) & 1;

    for (int ch = 0; ch < NCHUNK; ch++) {
        CP_WAIT2();
        __syncthreads();
        if (ch + 3 < NCHUNK) load_stage(ch + 3);
        CP_COMMIT();

        uint32_t sa  = sb + (ch & 3) * STAGE_BYTES;
        uint32_t sbb = sa + STAGE_A;
#pragma unroll
        for (int s = 0; s < 4; s++) {
            uint32_t a[2][4], b[2][4];
#pragma unroll
            for (int h = 0; h < 2; h++) {
                int r = 32 * wm + 16 * h + a_r;
                int kc = 2 * s + a_ksel;
                ldsm4(a[h][0], a[h][1], a[h][2], a[h][3],
                      sa + r * 128 + ((kc ^ (r & 7)) << 4));
            }
#pragma unroll
            for (int j = 0; j < 2; j++) {
                int n = 32 * wn + 16 * j + b_n;
                int kc = 2 * s + b_ksel;
                ldsm4(b[j][0], b[j][1], b[j][2], b[j][3],
                      sbb + n * 128 + ((kc ^ (n & 7)) << 4));
            }
#pragma unroll
            for (int mi = 0; mi < 2; mi++)
#pragma unroll
                for (int ni = 0; ni < 4; ni++)
                    mma16816(c[mi][ni], a[mi], &b[ni >> 1][(ni & 1) * 2]);
        }

        // ---- streamed PAc contraction: 4 (n,p) pairs per chunk, hidden under MMA ----
        if constexpr (MODE == 1) {
            int base = ch * 4;
            if (base < 256) {
#pragma unroll
                for (int u = 0; u < 4; u++) {
                    int idx = base + u;
                    int i = idx >> 4, p = idx & 15;
                    int nl = w + 8 * i;
                    float wv = sW[nl * 16 + p];
                    const float2 v = *(const float2*)(
                        g_PA + ((size_t)(rowBase + nl) * 16 + p) * G4 + colBase + 2 * lane);
                    accPA[i].x += wv * v.x;
                    accPA[i].y += wv * v.y;
                }
            }
        }
    }

    // ---- stage accumulators through smem (stride 68 floats) ----
    __syncthreads();
    float* Csm = (float*)smem;               // [128][68]
    const int gq = lane >> 2, tq = lane & 3;
#pragma unroll
    for (int mi = 0; mi < 2; mi++)
#pragma unroll
        for (int ni = 0; ni < 4; ni++) {
            int R = 32 * wm + 16 * mi + gq;
            int C = 32 * wn + 8 * ni + 2 * tq;
            *(float2*)&Csm[R * 68 + C]       = make_float2(c[mi][ni][0], c[mi][ni][1]);
            *(float2*)&Csm[(R + 8) * 68 + C] = make_float2(c[mi][ni][2], c[mi][ni][3]);
        }

    if constexpr (MODE == 0) {
        // ---- PA store: natural coalesced layout PA[(n*16+p)][jg] ----
        __syncthreads();
#pragma unroll
        for (int i2 = 0; i2 < 8; i2++) {
            int idx = tid + i2 * 256;
            int row = idx >> 4, jl = idx & 15;
            float4 v = *(const float4*)&Csm[row * 68 + jl * 4];
            *(float4*)(g_PA + (size_t)(rowBase + row) * G4 + colBase + jl * 4) = v;
        }
    } else {
        // write PAc accumulators to padded smem [128][68]
        float* sPAc = (float*)(smem + PAC_OFF);
#pragma unroll
        for (int i = 0; i < 16; i++) {
            int nl = w + 8 * i;
            *(float2*)&sPAc[nl * 68 + 2 * lane] = accPA[i];
        }
        __syncthreads();

        // ---- LSTM gate epilogue ----
        const int row = tid >> 1;            // 0..127
        const int jh  = tid & 1;
        const int n   = rowBase + row;
        const int jBase = colBase >> 2;
#pragma unroll
        for (int jj = 0; jj < 8; jj++) {
            int jl = jh * 8 + jj;            // 0..15
            int j  = jBase + jl;
            float4 v   = *(const float4*)&Csm[row * 68 + jl * 4];
            float4 pav = *(const float4*)&sPAc[row * 68 + jl * 4];
            float4 bv  = ((const float4*)g_b4)[j];
            float ig = sigmoidf_(v.x + pav.x + bv.x);
            float fg = sigmoidf_(v.y + pav.y + bv.y);
            float og = sigmoidf_(v.z + pav.z + bv.z);
            float gg = tanhf(v.w + pav.w + bv.w);
            size_t hidx = (size_t)n * H_ + j;
            float cn = fg * g_c[hidx] + ig * gg;
            float hn = og * tanhf(cn);
            g_c[hidx] = cn;
            g_h[hidx] = hn;
            __nv_bfloat16 hi, lo;
            split_bf16(hn, hi, lo);
            g_hh[hidx] = hi;
            g_hl[hidx] = lo;
            out[((size_t)n * T_ + t) * H_ + j] = hn;
        }
    }
}

// ---------------- host launch ----------------
extern "C" void kernel_launch(void* const* d_in, const int* in_sizes, int n_in,
                              void* d_out, int out_size) {
    const float* x     = (const float*)d_in[0];
    const float* A     = (const float*)d_in[1];
    const float* Wx    = (const float*)d_in[2];
    const float* Wh    = (const float*)d_in[3];
    const float* Wattn = (const float*)d_in[4];
    const float* b     = (const float*)d_in[5];
    float* out = (float*)d_out;

    cudaFuncSetAttribute(gemm3_kernel<0>, cudaFuncAttributeMaxDynamicSharedMemorySize, GEMM_SMEM);
    cudaFuncSetAttribute(gemm3_kernel<1>, cudaFuncAttributeMaxDynamicSharedMemorySize, GEMM_SMEM);

    split_x_kernel<<<(N_ * T_ * D_ + 255) / 256, 256>>>(x);
    split_w_kernel<<<(int)(((size_t)G4 * KTOT + 255) / 256), 256>>>(Wx, Wh);
    split_wattn_kernel<<<(int)(((size_t)G4 * H_ + 255) / 256), 256>>>(Wattn);
    split_at_kernel<<<(4096 * H_ + 255) / 256, 256>>>(A);
    prep_b_kernel<<<(G4 + 255) / 256, 256>>>(b);
    init_kernel<<<(N_ * H_ + 255) / 256, 256>>>(A);

    // PA = At @ Wattn_gi  (one-time, 3-pass bf16, fp32 out, coalesced layout)
    gemm3_kernel<0><<<dim3(G4 / BN_, 4096 / BM_), 256, GEMM_SMEM>>>(nullptr, 0);

    for (int t = 0; t < T_; t++) {
        score_kernel<<<N_, 256>>>(A);
        gemm3_kernel<1><<<dim3(G4 / BN_, N_ / BM_), 256, GEMM_SMEM>>>(out, t);
    }
}

// round 12
// speedup vs baseline: 1.3049x; 1.3049x over previous
#include <cuda_runtime.h>
#include <cuda_bf16.h>
#include <math.h>
#include <stdint.h>

// Problem constants
#define N_   256
#define T_   128
#define D_   512
#define H_   1024
#define KTOT 1536          // D + H  (x | h concat; attention folded into PA/PAc)
#define G4   4096          // 4*H gate columns

// GEMM tiling: CTA 128(M) x 64(N), K chunks of 64
#define BM_  128
#define BN_  64
#define KC   64
#define STAGES 4
#define STAGE_A 16384      // 128 rows * 128B
#define STAGE_B 8192       // 64 rows * 128B
#define STAGE_BYTES (STAGE_A + STAGE_B)
#define GEMM_SMEM (STAGES * STAGE_BYTES)   // 98304

// ---------------- persistent device scratch ----------------
__device__ __nv_bfloat16 g_xh[N_ * T_ * D_];          // x splits  [n][t][d]
__device__ __nv_bfloat16 g_xl[N_ * T_ * D_];
__device__ __nv_bfloat16 g_wh[(size_t)G4 * KTOT];     // [col][k] gate-interleaved [Wx;Wh]
__device__ __nv_bfloat16 g_wl[(size_t)G4 * KTOT];
__device__ __nv_bfloat16 g_wah[(size_t)G4 * H_];      // Wattn gate-interleaved [col][k]
__device__ __nv_bfloat16 g_wal[(size_t)G4 * H_];
__device__ __nv_bfloat16 g_ath[4096 * H_];            // A^T splits: row = n*16+p, k = h
__device__ __nv_bfloat16 g_atl[4096 * H_];
__device__ __nv_bfloat16 g_hh[N_ * H_];               // h splits
__device__ __nv_bfloat16 g_hl[N_ * H_];
__device__ float g_PA[(size_t)4096 * G4];             // [(n*16+p)][jg]  67MB fp32, coalesced
__device__ float g_PAc[(size_t)N_ * G4];              // [n][jg] contracted attention preacts
__device__ float g_h[N_ * H_];
__device__ float g_c[N_ * H_];
__device__ float g_b4[G4];                            // [j][gate]

// ---------------- helpers ----------------
__device__ __forceinline__ uint32_t smem_u32(const void* p) {
    uint32_t a;
    asm("{ .reg .u64 t; cvta.to.shared.u64 t, %1; cvt.u32.u64 %0, t; }" : "=r"(a) : "l"(p));
    return a;
}
__device__ __forceinline__ void cp_async16(uint32_t dst, const void* src) {
    asm volatile("cp.async.cg.shared.global [%0], [%1], 16;" :: "r"(dst), "l"(src));
}
#define CP_COMMIT() asm volatile("cp.async.commit_group;" ::: "memory")
#define CP_WAIT2()  asm volatile("cp.async.wait_group 2;" ::: "memory")

__device__ __forceinline__ void ldsm4(uint32_t& r0, uint32_t& r1, uint32_t& r2, uint32_t& r3,
                                      uint32_t addr) {
    asm volatile("ldmatrix.sync.aligned.m8n8.x4.shared.b16 {%0,%1,%2,%3}, [%4];"
                 : "=r"(r0), "=r"(r1), "=r"(r2), "=r"(r3) : "r"(addr));
}
__device__ __forceinline__ void mma16816(float* c, const uint32_t* a, const uint32_t* b) {
    asm volatile("mma.sync.aligned.m16n8k16.row.col.f32.bf16.bf16.f32 "
                 "{%0,%1,%2,%3}, {%4,%5,%6,%7}, {%8,%9}, {%0,%1,%2,%3};"
                 : "+f"(c[0]), "+f"(c[1]), "+f"(c[2]), "+f"(c[3])
                 : "r"(a[0]), "r"(a[1]), "r"(a[2]), "r"(a[3]), "r"(b[0]), "r"(b[1]));
}
__device__ __forceinline__ float sigmoidf_(float x) { return 1.0f / (1.0f + expf(-x)); }
__device__ __forceinline__ void split_bf16(float v, __nv_bfloat16& hi, __nv_bfloat16& lo) {
    hi = __float2bfloat16_rn(v);
    lo = __float2bfloat16_rn(v - __bfloat162float(hi));
}

// ---------------- prep kernels ----------------
__global__ void __launch_bounds__(256) split_x_kernel(const float* __restrict__ x) {
    int idx = blockIdx.x * 256 + threadIdx.x;
    if (idx >= N_ * T_ * D_) return;
    __nv_bfloat16 hi, lo;
    split_bf16(x[idx], hi, lo);
    g_xh[idx] = hi;
    g_xl[idx] = lo;
}

// [Wx;Wh] -> gate-interleaved transposed [col][k], col = j*4+g
__global__ void __launch_bounds__(256) split_w_kernel(
    const float* __restrict__ Wx, const float* __restrict__ Wh) {
    size_t idx = (size_t)blockIdx.x * 256 + threadIdx.x;
    if (idx >= (size_t)G4 * KTOT) return;
    int col = (int)(idx / KTOT);
    int k   = (int)(idx % KTOT);
    int j = col >> 2, g = col & 3;
    float v = (k < D_) ? Wx[(size_t)k * G4 + g * H_ + j]
                       : Wh[(size_t)(k - D_) * G4 + g * H_ + j];
    __nv_bfloat16 hi, lo;
    split_bf16(v, hi, lo);
    g_wh[idx] = hi;
    g_wl[idx] = lo;
}

__global__ void __launch_bounds__(256) split_wattn_kernel(const float* __restrict__ Wattn) {
    size_t idx = (size_t)blockIdx.x * 256 + threadIdx.x;
    if (idx >= (size_t)G4 * H_) return;
    int col = (int)(idx / H_);
    int k   = (int)(idx % H_);
    int j = col >> 2, g = col & 3;
    float v = Wattn[(size_t)k * G4 + g * H_ + j];
    __nv_bfloat16 hi, lo;
    split_bf16(v, hi, lo);
    g_wah[idx] = hi;
    g_wal[idx] = lo;
}

// A[n][h][p] -> At[(n*16+p)][h] bf16 splits
__global__ void __launch_bounds__(256) split_at_kernel(const float* __restrict__ A) {
    int idx = blockIdx.x * 256 + threadIdx.x;    // idx = r*1024 + h
    if (idx >= 4096 * H_) return;
    int r = idx >> 10, h = idx & 1023;
    int n = r >> 4, p = r & 15;
    float v = A[((size_t)n * H_ + h) * 16 + p];
    __nv_bfloat16 hi, lo;
    split_bf16(v, hi, lo);
    g_ath[idx] = hi;
    g_atl[idx] = lo;
}

__global__ void prep_b_kernel(const float* __restrict__ b) {
    int idx = blockIdx.x * 256 + threadIdx.x;    // idx = j*4+g
    if (idx >= G4) return;
    g_b4[idx] = b[(idx & 3) * H_ + (idx >> 2)];
}

__global__ void __launch_bounds__(256) init_kernel(const float* __restrict__ A) {
    int idx = blockIdx.x * 256 + threadIdx.x;    // idx = n*H + h
    if (idx >= N_ * H_) return;
    const float4* ap = (const float4*)(A + (size_t)idx * 16);
    float4 a0 = ap[0], a1 = ap[1], a2 = ap[2], a3 = ap[3];
    float s = a0.x + a0.y + a0.z + a0.w + a1.x + a1.y + a1.z + a1.w +
              a2.x + a2.y + a2.z + a2.w + a3.x + a3.y + a3.z + a3.w;
    float m = s * (1.0f / 16.0f);
    g_h[idx] = m;
    g_c[idx] = m;
    __nv_bfloat16 hi, lo;
    split_bf16(m, hi, lo);
    g_hh[idx] = hi;
    g_hl[idx] = lo;
}

// ---------------- per-step: scores + softmax + PAc contraction ----------------
// One CTA per n. After softmax (w16 in smem), contract the 16 precomputed
// PA rows for this n into PAc[n][0..4095] with fully coalesced float4 loads.
__global__ void __launch_bounds__(256) score_pac_kernel(const float* __restrict__ A) {
    __shared__ float sred[8][16];
    __shared__ float sw16[16];
    int n = blockIdx.x, tid = threadIdx.x;
    const float* Ab = A + (size_t)n * H_ * 16;
    const float* hb = g_h + (size_t)n * H_;

    float s[16];
#pragma unroll
    for (int p = 0; p < 16; p++) s[p] = 0.0f;
#pragma unroll
    for (int rr = 0; rr < 4; rr++) {
        int row = tid + rr * 256;
        const float4* ap = (const float4*)(Ab + (size_t)row * 16);
        float4 a0 = ap[0], a1 = ap[1], a2 = ap[2], a3 = ap[3];
        float hv = hb[row];
        s[0]  += hv * a0.x; s[1]  += hv * a0.y; s[2]  += hv * a0.z; s[3]  += hv * a0.w;
        s[4]  += hv * a1.x; s[5]  += hv * a1.y; s[6]  += hv * a1.z; s[7]  += hv * a1.w;
        s[8]  += hv * a2.x; s[9]  += hv * a2.y; s[10] += hv * a2.z; s[11] += hv * a2.w;
        s[12] += hv * a3.x; s[13] += hv * a3.y; s[14] += hv * a3.z; s[15] += hv * a3.w;
    }
#pragma unroll
    for (int p = 0; p < 16; p++) {
#pragma unroll
        for (int off = 16; off > 0; off >>= 1)
            s[p] += __shfl_down_sync(0xFFFFFFFF, s[p], off);
    }
    int lane = tid & 31, w = tid >> 5;
    if (lane == 0) {
#pragma unroll
        for (int p = 0; p < 16; p++) sred[w][p] = s[p];
    }
    __syncthreads();
    if (tid == 0) {
        float sc[16], mx = -1e30f;
#pragma unroll
        for (int p = 0; p < 16; p++) {
            float t = 0.0f;
#pragma unroll
            for (int ww = 0; ww < 8; ww++) t += sred[ww][p];
            sc[p] = t * (1.0f / 32.0f);          // / sqrt(H)
            mx = fmaxf(mx, sc[p]);
        }
        float se = 0.0f;
#pragma unroll
        for (int p = 0; p < 16; p++) { sc[p] = expf(sc[p] - mx); se += sc[p]; }
        float inv = 1.0f / se;
#pragma unroll
        for (int p = 0; p < 16; p++) sw16[p] = sc[p] * inv;
    }
    __syncthreads();

    float wv[16];
#pragma unroll
    for (int p = 0; p < 16; p++) wv[p] = sw16[p];

    // PAc[n][jg] = sum_p wv[p] * PA[n*16+p][jg] — coalesced float4 streams
    const float* pa = g_PA + (size_t)n * 16 * G4;
    float* pc = g_PAc + (size_t)n * G4;
#pragma unroll
    for (int cg = 0; cg < 4; cg++) {
        int col = cg * 1024 + tid * 4;
        float4 acc = make_float4(0.0f, 0.0f, 0.0f, 0.0f);
#pragma unroll
        for (int p = 0; p < 16; p++) {
            float4 v = *(const float4*)(pa + (size_t)p * G4 + col);
            acc.x += wv[p] * v.x;
            acc.y += wv[p] * v.y;
            acc.z += wv[p] * v.z;
            acc.w += wv[p] * v.w;
        }
        *(float4*)(pc + col) = acc;
    }
}

// ---------------- 3-pass split-bf16 GEMM (mma.sync), 2 modes ----------------
// MODE 0: PA precompute  PA[r=(n*16+p)][jg] = At[r,:] . Wattn_gi[jg,:]  (K=1024)
// MODE 1: recurrent step C[n][jg] = [x_t|h][n,:] . [Wx;Wh]_gi[jg,:]    (K=1536)
//         epilogue: C + PAc[n][jg] + bias -> LSTM gates -> c,h,out
// grid: (G4/BN_, Mtiles). 256 threads, warps 4(M) x 2(N), warp tile 32x32.
template <int MODE>
__global__ void __launch_bounds__(256, 1) gemm3_kernel(float* __restrict__ out, int t) {
    constexpr int SEGC   = (MODE == 0) ? (H_ / KC) : (KTOT / KC);   // 16 : 24
    constexpr int NCHUNK = 3 * SEGC;                                 // 48 : 72

    extern __shared__ char smem[];
    uint32_t sb = smem_u32(smem);
    const int tid = threadIdx.x;
    const int rowBase = blockIdx.y * BM_;
    const int colBase = blockIdx.x * BN_;
    const int w = tid >> 5, lane = tid & 31;
    const int wm = w & 3, wn = w >> 2;

    float c[2][4][4];
#pragma unroll
    for (int mi = 0; mi < 2; mi++)
#pragma unroll
        for (int ni = 0; ni < 4; ni++)
#pragma unroll
            for (int q = 0; q < 4; q++) c[mi][ni][q] = 0.0f;

    auto load_stage = [&](int ch) {
        int s = ch & 3;
        int seg = ch / SEGC;                 // 0: Ah*Bh, 1: Al*Bh, 2: Ah*Bl
        int kp = (ch % SEGC) * KC;
        uint32_t sa  = sb + s * STAGE_BYTES;
        uint32_t sbb = sa + STAGE_A;
#pragma unroll
        for (int i = 0; i < 4; i++) {
            int o = tid + i * 256;
            int r = o >> 3, kc = o & 7;
            int k = kp + kc * 8;
            const __nv_bfloat16* src;
            if constexpr (MODE == 0) {
                const __nv_bfloat16* ab = (seg == 1) ? g_atl : g_ath;
                src = ab + (size_t)(rowBase + r) * H_ + k;
            } else {
                if (k < D_) {
                    const __nv_bfloat16* xp = (seg == 1) ? g_xl : g_xh;
                    src = xp + ((size_t)(rowBase + r) * T_ + t) * D_ + k;
                } else {
                    const __nv_bfloat16* hp = (seg == 1) ? g_hl : g_hh;
                    src = hp + (size_t)(rowBase + r) * H_ + (k - D_);
                }
            }
            cp_async16(sa + r * 128 + ((kc ^ (r & 7)) << 4), src);
        }
#pragma unroll
        for (int i = 0; i < 2; i++) {
            int o = tid + i * 256;
            int r = o >> 3, kc = o & 7;
            const __nv_bfloat16* src;
            if constexpr (MODE == 0) {
                const __nv_bfloat16* wb = (seg == 2) ? g_wal : g_wah;
                src = wb + (size_t)(colBase + r) * H_ + kp + kc * 8;
            } else {
                const __nv_bfloat16* wb = (seg == 2) ? g_wl : g_wh;
                src = wb + (size_t)(colBase + r) * KTOT + kp + kc * 8;
            }
            cp_async16(sbb + r * 128 + ((kc ^ (r & 7)) << 4), src);
        }
    };

    load_stage(0); CP_COMMIT();
    load_stage(1); CP_COMMIT();
    load_stage(2); CP_COMMIT();

    const int a_r    = (lane & 15);
    const int a_ksel = (lane >> 4);
    const int b_n    = (lane & 7) + ((lane >> 4) << 3);
    const int b_ksel = (lane >> 3) & 1;

    for (int ch = 0; ch < NCHUNK; ch++) {
        CP_WAIT2();
        __syncthreads();
        if (ch + 3 < NCHUNK) load_stage(ch + 3);
        CP_COMMIT();

        uint32_t sa  = sb + (ch & 3) * STAGE_BYTES;
        uint32_t sbb = sa + STAGE_A;
#pragma unroll
        for (int s = 0; s < 4; s++) {
            uint32_t a[2][4], b[2][4];
#pragma unroll
            for (int h = 0; h < 2; h++) {
                int r = 32 * wm + 16 * h + a_r;
                int kc = 2 * s + a_ksel;
                ldsm4(a[h][0], a[h][1], a[h][2], a[h][3],
                      sa + r * 128 + ((kc ^ (r & 7)) << 4));
            }
#pragma unroll
            for (int j = 0; j < 2; j++) {
                int n = 32 * wn + 16 * j + b_n;
                int kc = 2 * s + b_ksel;
                ldsm4(b[j][0], b[j][1], b[j][2], b[j][3],
                      sbb + n * 128 + ((kc ^ (n & 7)) << 4));
            }
#pragma unroll
            for (int mi = 0; mi < 2; mi++)
#pragma unroll
                for (int ni = 0; ni < 4; ni++)
                    mma16816(c[mi][ni], a[mi], &b[ni >> 1][(ni & 1) * 2]);
        }
    }

    // ---- stage accumulators through smem (stride 68 floats) ----
    __syncthreads();
    float* Csm = (float*)smem;               // [128][68]
    const int gq = lane >> 2, tq = lane & 3;
#pragma unroll
    for (int mi = 0; mi < 2; mi++)
#pragma unroll
        for (int ni = 0; ni < 4; ni++) {
            int R = 32 * wm + 16 * mi + gq;
            int C = 32 * wn + 8 * ni + 2 * tq;
            *(float2*)&Csm[R * 68 + C]       = make_float2(c[mi][ni][0], c[mi][ni][1]);
            *(float2*)&Csm[(R + 8) * 68 + C] = make_float2(c[mi][ni][2], c[mi][ni][3]);
        }
    __syncthreads();

    if constexpr (MODE == 0) {
        // ---- PA store: natural coalesced layout PA[(n*16+p)][jg] ----
#pragma unroll
        for (int i2 = 0; i2 < 8; i2++) {
            int idx = tid + i2 * 256;
            int row = idx >> 4, jl = idx & 15;
            float4 v = *(const float4*)&Csm[row * 68 + jl * 4];
            *(float4*)(g_PA + (size_t)(rowBase + row) * G4 + colBase + jl * 4) = v;
        }
    } else {
        // ---- LSTM gate epilogue: C + PAc + bias ----
        const int row = tid >> 1;            // 0..127
        const int jh  = tid & 1;
        const int n   = rowBase + row;
        const int jBase = colBase >> 2;
        const float* pc = g_PAc + (size_t)n * G4 + colBase;
#pragma unroll
        for (int jj = 0; jj < 8; jj++) {
            int jl = jh * 8 + jj;            // 0..15
            int j  = jBase + jl;
            float4 v   = *(const float4*)&Csm[row * 68 + jl * 4];
            float4 pav = *(const float4*)(pc + jl * 4);
            float4 bv  = ((const float4*)g_b4)[j];
            float ig = sigmoidf_(v.x + pav.x + bv.x);
            float fg = sigmoidf_(v.y + pav.y + bv.y);
            float og = sigmoidf_(v.z + pav.z + bv.z);
            float gg = tanhf(v.w + pav.w + bv.w);
            size_t hidx = (size_t)n * H_ + j;
            float cn = fg * g_c[hidx] + ig * gg;
            float hn = og * tanhf(cn);
            g_c[hidx] = cn;
            g_h[hidx] = hn;
            __nv_bfloat16 hi, lo;
            split_bf16(hn, hi, lo);
            g_hh[hidx] = hi;
            g_hl[hidx] = lo;
            out[((size_t)n * T_ + t) * H_ + j] = hn;
        }
    }
}

// ---------------- host launch ----------------
extern "C" void kernel_launch(void* const* d_in, const int* in_sizes, int n_in,
                              void* d_out, int out_size) {
    const float* x     = (const float*)d_in[0];
    const float* A     = (const float*)d_in[1];
    const float* Wx    = (const float*)d_in[2];
    const float* Wh    = (const float*)d_in[3];
    const float* Wattn = (const float*)d_in[4];
    const float* b     = (const float*)d_in[5];
    float* out = (float*)d_out;

    cudaFuncSetAttribute(gemm3_kernel<0>, cudaFuncAttributeMaxDynamicSharedMemorySize, GEMM_SMEM);
    cudaFuncSetAttribute(gemm3_kernel<1>, cudaFuncAttributeMaxDynamicSharedMemorySize, GEMM_SMEM);

    split_x_kernel<<<(N_ * T_ * D_ + 255) / 256, 256>>>(x);
    split_w_kernel<<<(int)(((size_t)G4 * KTOT + 255) / 256), 256>>>(Wx, Wh);
    split_wattn_kernel<<<(int)(((size_t)G4 * H_ + 255) / 256), 256>>>(Wattn);
    split_at_kernel<<<(4096 * H_ + 255) / 256, 256>>>(A);
    prep_b_kernel<<<(G4 + 255) / 256, 256>>>(b);
    init_kernel<<<(N_ * H_ + 255) / 256, 256>>>(A);

    // PA = At @ Wattn_gi  (one-time, 3-pass bf16, fp32 out, coalesced layout)
    gemm3_kernel<0><<<dim3(G4 / BN_, 4096 / BM_), 256, GEMM_SMEM>>>(nullptr, 0);

    for (int t = 0; t < T_; t++) {
        score_pac_kernel<<<N_, 256>>>(A);
        gemm3_kernel<1><<<dim3(G4 / BN_, N_ / BM_), 256, GEMM_SMEM>>>(out, t);
    }
}

// round 17
// speedup vs baseline: 1.9345x; 1.4825x over previous
#include <cuda_runtime.h>
#include <cuda_bf16.h>
#include <math.h>
#include <stdint.h>

// Problem constants
#define N_   256
#define T_   128
#define D_   512
#define H_   1024
#define KTOT 1536          // D + H  (x | h concat; attention folded into PA/PAc)
#define G4   4096          // 4*H gate columns

// GEMM tiling: CTA 128(M) x 64(N), K chunks of 64
#define BM_  128
#define BN_  64
#define KC   64
#define STAGES 4
#define STAGE_A 16384      // 128 rows * 128B
#define STAGE_B 8192       // 64 rows * 128B
#define STAGE_BYTES (STAGE_A + STAGE_B)
#define GEMM_SMEM (STAGES * STAGE_BYTES)   // 98304

// ---------------- persistent device scratch ----------------
__device__ __nv_bfloat16 g_xh[N_ * T_ * D_];          // x splits  [n][t][d]
__device__ __nv_bfloat16 g_xl[N_ * T_ * D_];
__device__ __nv_bfloat16 g_wh[(size_t)G4 * KTOT];     // [col][k] gate-interleaved [Wx;Wh]
__device__ __nv_bfloat16 g_wl[(size_t)G4 * KTOT];
__device__ __nv_bfloat16 g_wah[(size_t)G4 * H_];      // Wattn gate-interleaved [col][k]
__device__ __nv_bfloat16 g_wal[(size_t)G4 * H_];
__device__ __nv_bfloat16 g_ath[4096 * H_];            // A^T splits: row = n*16+p, k = h
__device__ __nv_bfloat16 g_atl[4096 * H_];
__device__ __nv_bfloat16 g_hh[N_ * H_];               // h splits
__device__ __nv_bfloat16 g_hl[N_ * H_];
__device__ float g_PA[(size_t)4096 * G4];             // [(n*16+p)][jg]  67MB fp32, coalesced
__device__ float g_PAc[(size_t)N_ * G4];              // [n][jg] contracted attention preacts
__device__ float g_w16[N_ * 16];                      // softmax attention weights
__device__ float g_h[N_ * H_];
__device__ float g_c[N_ * H_];
__device__ float g_b4[G4];                            // [j][gate]

// ---------------- helpers ----------------
__device__ __forceinline__ uint32_t smem_u32(const void* p) {
    uint32_t a;
    asm("{ .reg .u64 t; cvta.to.shared.u64 t, %1; cvt.u32.u64 %0, t; }" : "=r"(a) : "l"(p));
    return a;
}
__device__ __forceinline__ void cp_async16(uint32_t dst, const void* src) {
    asm volatile("cp.async.cg.shared.global [%0], [%1], 16;" :: "r"(dst), "l"(src));
}
#define CP_COMMIT() asm volatile("cp.async.commit_group;" ::: "memory")
#define CP_WAIT2()  asm volatile("cp.async.wait_group 2;" ::: "memory")

__device__ __forceinline__ void ldsm4(uint32_t& r0, uint32_t& r1, uint32_t& r2, uint32_t& r3,
                                      uint32_t addr) {
    asm volatile("ldmatrix.sync.aligned.m8n8.x4.shared.b16 {%0,%1,%2,%3}, [%4];"
                 : "=r"(r0), "=r"(r1), "=r"(r2), "=r"(r3) : "r"(addr));
}
__device__ __forceinline__ void mma16816(float* c, const uint32_t* a, const uint32_t* b) {
    asm volatile("mma.sync.aligned.m16n8k16.row.col.f32.bf16.bf16.f32 "
                 "{%0,%1,%2,%3}, {%4,%5,%6,%7}, {%8,%9}, {%0,%1,%2,%3};"
                 : "+f"(c[0]), "+f"(c[1]), "+f"(c[2]), "+f"(c[3])
                 : "r"(a[0]), "r"(a[1]), "r"(a[2]), "r"(a[3]), "r"(b[0]), "r"(b[1]));
}
__device__ __forceinline__ float sigmoidf_(float x) { return 1.0f / (1.0f + expf(-x)); }
__device__ __forceinline__ void split_bf16(float v, __nv_bfloat16& hi, __nv_bfloat16& lo) {
    hi = __float2bfloat16_rn(v);
    lo = __float2bfloat16_rn(v - __bfloat162float(hi));
}

// ---------------- prep kernels ----------------
__global__ void __launch_bounds__(256) split_x_kernel(const float* __restrict__ x) {
    int idx = blockIdx.x * 256 + threadIdx.x;
    if (idx >= N_ * T_ * D_) return;
    __nv_bfloat16 hi, lo;
    split_bf16(x[idx], hi, lo);
    g_xh[idx] = hi;
    g_xl[idx] = lo;
}

// [Wx;Wh] -> gate-interleaved transposed [col][k], col = j*4+g
__global__ void __launch_bounds__(256) split_w_kernel(
    const float* __restrict__ Wx, const float* __restrict__ Wh) {
    size_t idx = (size_t)blockIdx.x * 256 + threadIdx.x;
    if (idx >= (size_t)G4 * KTOT) return;
    int col = (int)(idx / KTOT);
    int k   = (int)(idx % KTOT);
    int j = col >> 2, g = col & 3;
    float v = (k < D_) ? Wx[(size_t)k * G4 + g * H_ + j]
                       : Wh[(size_t)(k - D_) * G4 + g * H_ + j];
    __nv_bfloat16 hi, lo;
    split_bf16(v, hi, lo);
    g_wh[idx] = hi;
    g_wl[idx] = lo;
}

__global__ void __launch_bounds__(256) split_wattn_kernel(const float* __restrict__ Wattn) {
    size_t idx = (size_t)blockIdx.x * 256 + threadIdx.x;
    if (idx >= (size_t)G4 * H_) return;
    int col = (int)(idx / H_);
    int k   = (int)(idx % H_);
    int j = col >> 2, g = col & 3;
    float v = Wattn[(size_t)k * G4 + g * H_ + j];
    __nv_bfloat16 hi, lo;
    split_bf16(v, hi, lo);
    g_wah[idx] = hi;
    g_wal[idx] = lo;
}

// A[n][h][p] -> At[(n*16+p)][h] bf16 splits
__global__ void __launch_bounds__(256) split_at_kernel(const float* __restrict__ A) {
    int idx = blockIdx.x * 256 + threadIdx.x;    // idx = r*1024 + h
    if (idx >= 4096 * H_) return;
    int r = idx >> 10, h = idx & 1023;
    int n = r >> 4, p = r & 15;
    float v = A[((size_t)n * H_ + h) * 16 + p];
    __nv_bfloat16 hi, lo;
    split_bf16(v, hi, lo);
    g_ath[idx] = hi;
    g_atl[idx] = lo;
}

__global__ void prep_b_kernel(const float* __restrict__ b) {
    int idx = blockIdx.x * 256 + threadIdx.x;    // idx = j*4+g
    if (idx >= G4) return;
    g_b4[idx] = b[(idx & 3) * H_ + (idx >> 2)];
}

__global__ void __launch_bounds__(256) init_kernel(const float* __restrict__ A) {
    int idx = blockIdx.x * 256 + threadIdx.x;    // idx = n*H + h
    if (idx >= N_ * H_) return;
    const float4* ap = (const float4*)(A + (size_t)idx * 16);
    float4 a0 = ap[0], a1 = ap[1], a2 = ap[2], a3 = ap[3];
    float s = a0.x + a0.y + a0.z + a0.w + a1.x + a1.y + a1.z + a1.w +
              a2.x + a2.y + a2.z + a2.w + a3.x + a3.y + a3.z + a3.w;
    float m = s * (1.0f / 16.0f);
    g_h[idx] = m;
    g_c[idx] = m;
    __nv_bfloat16 hi, lo;
    split_bf16(m, hi, lo);
    g_hh[idx] = hi;
    g_hl[idx] = lo;
}

// ---------------- per-step: scores + softmax (tiny, 256 CTAs) ----------------
__global__ void __launch_bounds__(256) score_kernel(const float* __restrict__ A) {
    __shared__ float sred[8][16];
    int n = blockIdx.x, tid = threadIdx.x;
    const float* Ab = A + (size_t)n * H_ * 16;
    const float* hb = g_h + (size_t)n * H_;

    float s[16];
#pragma unroll
    for (int p = 0; p < 16; p++) s[p] = 0.0f;
#pragma unroll
    for (int rr = 0; rr < 4; rr++) {
        int row = tid + rr * 256;
        const float4* ap = (const float4*)(Ab + (size_t)row * 16);
        float4 a0 = ap[0], a1 = ap[1], a2 = ap[2], a3 = ap[3];
        float hv = hb[row];
        s[0]  += hv * a0.x; s[1]  += hv * a0.y; s[2]  += hv * a0.z; s[3]  += hv * a0.w;
        s[4]  += hv * a1.x; s[5]  += hv * a1.y; s[6]  += hv * a1.z; s[7]  += hv * a1.w;
        s[8]  += hv * a2.x; s[9]  += hv * a2.y; s[10] += hv * a2.z; s[11] += hv * a2.w;
        s[12] += hv * a3.x; s[13] += hv * a3.y; s[14] += hv * a3.z; s[15] += hv * a3.w;
    }
#pragma unroll
    for (int p = 0; p < 16; p++) {
#pragma unroll
        for (int off = 16; off > 0; off >>= 1)
            s[p] += __shfl_down_sync(0xFFFFFFFF, s[p], off);
    }
    int lane = tid & 31, w = tid >> 5;
    if (lane == 0) {
#pragma unroll
        for (int p = 0; p < 16; p++) sred[w][p] = s[p];
    }
    __syncthreads();
    if (tid == 0) {
        float sc[16], mx = -1e30f;
#pragma unroll
        for (int p = 0; p < 16; p++) {
            float t = 0.0f;
#pragma unroll
            for (int ww = 0; ww < 8; ww++) t += sred[ww][p];
            sc[p] = t * (1.0f / 32.0f);          // / sqrt(H)
            mx = fmaxf(mx, sc[p]);
        }
        float se = 0.0f;
#pragma unroll
        for (int p = 0; p < 16; p++) { sc[p] = expf(sc[p] - mx); se += sc[p]; }
        float inv = 1.0f / se;
#pragma unroll
        for (int p = 0; p < 16; p++) g_w16[n * 16 + p] = sc[p] * inv;
    }
}

// ---------------- per-step: PAc contraction (1024 CTAs, pure streaming) ----------------
// CTA = (n, 1024-col slice). PAc[n][col] = sum_p w16[n,p] * PA[n*16+p][col].
// Per CTA: 16 coalesced float4 streams of 4KB; MLP=16 per thread.
__global__ void __launch_bounds__(256) pac_kernel() {
    int bid = blockIdx.x;
    int n   = bid >> 2;
    int cg  = bid & 3;
    int col = cg * 1024 + threadIdx.x * 4;

    float wv[16];
    const float* w16 = g_w16 + n * 16;
#pragma unroll
    for (int p = 0; p < 16; p++) wv[p] = __ldg(w16 + p);

    const float* pa = g_PA + (size_t)n * 16 * G4 + col;
    float4 acc = make_float4(0.0f, 0.0f, 0.0f, 0.0f);
#pragma unroll
    for (int p = 0; p < 16; p++) {
        float4 v = *(const float4*)(pa + (size_t)p * G4);
        acc.x += wv[p] * v.x;
        acc.y += wv[p] * v.y;
        acc.z += wv[p] * v.z;
        acc.w += wv[p] * v.w;
    }
    *(float4*)(g_PAc + (size_t)n * G4 + col) = acc;
}

// ---------------- 3-pass split-bf16 GEMM (mma.sync), 2 modes ----------------
// MODE 0: PA precompute  PA[r=(n*16+p)][jg] = At[r,:] . Wattn_gi[jg,:]  (K=1024)
// MODE 1: recurrent step C[n][jg] = [x_t|h][n,:] . [Wx;Wh]_gi[jg,:]    (K=1536)
//         epilogue: C + PAc[n][jg] + bias -> LSTM gates -> c,h,out
// grid: (G4/BN_, Mtiles). 256 threads, warps 4(M) x 2(N), warp tile 32x32.
template <int MODE>
__global__ void __launch_bounds__(256, 1) gemm3_kernel(float* __restrict__ out, int t) {
    constexpr int SEGC   = (MODE == 0) ? (H_ / KC) : (KTOT / KC);   // 16 : 24
    constexpr int NCHUNK = 3 * SEGC;                                 // 48 : 72

    extern __shared__ char smem[];
    uint32_t sb = smem_u32(smem);
    const int tid = threadIdx.x;
    const int rowBase = blockIdx.y * BM_;
    const int colBase = blockIdx.x * BN_;
    const int w = tid >> 5, lane = tid & 31;
    const int wm = w & 3, wn = w >> 2;

    float c[2][4][4];
#pragma unroll
    for (int mi = 0; mi < 2; mi++)
#pragma unroll
        for (int ni = 0; ni < 4; ni++)
#pragma unroll
            for (int q = 0; q < 4; q++) c[mi][ni][q] = 0.0f;

    auto load_stage = [&](int ch) {
        int s = ch & 3;
        int seg = ch / SEGC;                 // 0: Ah*Bh, 1: Al*Bh, 2: Ah*Bl
        int kp = (ch % SEGC) * KC;
        uint32_t sa  = sb + s * STAGE_BYTES;
        uint32_t sbb = sa + STAGE_A;
#pragma unroll
        for (int i = 0; i < 4; i++) {
            int o = tid + i * 256;
            int r = o >> 3, kc = o & 7;
            int k = kp + kc * 8;
            const __nv_bfloat16* src;
            if constexpr (MODE == 0) {
                const __nv_bfloat16* ab = (seg == 1) ? g_atl : g_ath;
                src = ab + (size_t)(rowBase + r) * H_ + k;
            } else {
                if (k < D_) {
                    const __nv_bfloat16* xp = (seg == 1) ? g_xl : g_xh;
                    src = xp + ((size_t)(rowBase + r) * T_ + t) * D_ + k;
                } else {
                    const __nv_bfloat16* hp = (seg == 1) ? g_hl : g_hh;
                    src = hp + (size_t)(rowBase + r) * H_ + (k - D_);
                }
            }
            cp_async16(sa + r * 128 + ((kc ^ (r & 7)) << 4), src);
        }
#pragma unroll
        for (int i = 0; i < 2; i++) {
            int o = tid + i * 256;
            int r = o >> 3, kc = o & 7;
            const __nv_bfloat16* src;
            if constexpr (MODE == 0) {
                const __nv_bfloat16* wb = (seg == 2) ? g_wal : g_wah;
                src = wb + (size_t)(colBase + r) * H_ + kp + kc * 8;
            } else {
                const __nv_bfloat16* wb = (seg == 2) ? g_wl : g_wh;
                src = wb + (size_t)(colBase + r) * KTOT + kp + kc * 8;
            }
            cp_async16(sbb + r * 128 + ((kc ^ (r & 7)) << 4), src);
        }
    };

    load_stage(0); CP_COMMIT();
    load_stage(1); CP_COMMIT();
    load_stage(2); CP_COMMIT();

    const int a_r    = (lane & 15);
    const int a_ksel = (lane >> 4);
    const int b_n    = (lane & 7) + ((lane >> 4) << 3);
    const int b_ksel = (lane >> 3) & 1;

    for (int ch = 0; ch < NCHUNK; ch++) {
        CP_WAIT2();
        __syncthreads();
        if (ch + 3 < NCHUNK) load_stage(ch + 3);
        CP_COMMIT();

        uint32_t sa  = sb + (ch & 3) * STAGE_BYTES;
        uint32_t sbb = sa + STAGE_A;
#pragma unroll
        for (int s = 0; s < 4; s++) {
            uint32_t a[2][4], b[2][4];
#pragma unroll
            for (int h = 0; h < 2; h++) {
                int r = 32 * wm + 16 * h + a_r;
                int kc = 2 * s + a_ksel;
                ldsm4(a[h][0], a[h][1], a[h][2], a[h][3],
                      sa + r * 128 + ((kc ^ (r & 7)) << 4));
            }
#pragma unroll
            for (int j = 0; j < 2; j++) {
                int n = 32 * wn + 16 * j + b_n;
                int kc = 2 * s + b_ksel;
                ldsm4(b[j][0], b[j][1], b[j][2], b[j][3],
                      sbb + n * 128 + ((kc ^ (n & 7)) << 4));
            }
#pragma unroll
            for (int mi = 0; mi < 2; mi++)
#pragma unroll
                for (int ni = 0; ni < 4; ni++)
                    mma16816(c[mi][ni], a[mi], &b[ni >> 1][(ni & 1) * 2]);
        }
    }

    // ---- stage accumulators through smem (stride 68 floats) ----
    __syncthreads();
    float* Csm = (float*)smem;               // [128][68]
    const int gq = lane >> 2, tq = lane & 3;
#pragma unroll
    for (int mi = 0; mi < 2; mi++)
#pragma unroll
        for (int ni = 0; ni < 4; ni++) {
            int R = 32 * wm + 16 * mi + gq;
            int C = 32 * wn + 8 * ni + 2 * tq;
            *(float2*)&Csm[R * 68 + C]       = make_float2(c[mi][ni][0], c[mi][ni][1]);
            *(float2*)&Csm[(R + 8) * 68 + C] = make_float2(c[mi][ni][2], c[mi][ni][3]);
        }
    __syncthreads();

    if constexpr (MODE == 0) {
        // ---- PA store: natural coalesced layout PA[(n*16+p)][jg] ----
#pragma unroll
        for (int i2 = 0; i2 < 8; i2++) {
            int idx = tid + i2 * 256;
            int row = idx >> 4, jl = idx & 15;
            float4 v = *(const float4*)&Csm[row * 68 + jl * 4];
            *(float4*)(g_PA + (size_t)(rowBase + row) * G4 + colBase + jl * 4) = v;
        }
    } else {
        // ---- LSTM gate epilogue: C + PAc + bias ----
        const int row = tid >> 1;            // 0..127
        const int jh  = tid & 1;
        const int n   = rowBase + row;
        const int jBase = colBase >> 2;
        const float* pc = g_PAc + (size_t)n * G4 + colBase;
#pragma unroll
        for (int jj = 0; jj < 8; jj++) {
            int jl = jh * 8 + jj;            // 0..15
            int j  = jBase + jl;
            float4 v   = *(const float4*)&Csm[row * 68 + jl * 4];
            float4 pav = *(const float4*)(pc + jl * 4);
            float4 bv  = ((const float4*)g_b4)[j];
            float ig = sigmoidf_(v.x + pav.x + bv.x);
            float fg = sigmoidf_(v.y + pav.y + bv.y);
            float og = sigmoidf_(v.z + pav.z + bv.z);
            float gg = tanhf(v.w + pav.w + bv.w);
            size_t hidx = (size_t)n * H_ + j;
            float cn = fg * g_c[hidx] + ig * gg;
            float hn = og * tanhf(cn);
            g_c[hidx] = cn;
            g_h[hidx] = hn;
            __nv_bfloat16 hi, lo;
            split_bf16(hn, hi, lo);
            g_hh[hidx] = hi;
            g_hl[hidx] = lo;
            out[((size_t)n * T_ + t) * H_ + j] = hn;
        }
    }
}

// ---------------- host launch ----------------
extern "C" void kernel_launch(void* const* d_in, const int* in_sizes, int n_in,
                              void* d_out, int out_size) {
    const float* x     = (const float*)d_in[0];
    const float* A     = (const float*)d_in[1];
    const float* Wx    = (const float*)d_in[2];
    const float* Wh    = (const float*)d_in[3];
    const float* Wattn = (const float*)d_in[4];
    const float* b     = (const float*)d_in[5];
    float* out = (float*)d_out;

    cudaFuncSetAttribute(gemm3_kernel<0>, cudaFuncAttributeMaxDynamicSharedMemorySize, GEMM_SMEM);
    cudaFuncSetAttribute(gemm3_kernel<1>, cudaFuncAttributeMaxDynamicSharedMemorySize, GEMM_SMEM);

    split_x_kernel<<<(N_ * T_ * D_ + 255) / 256, 256>>>(x);
    split_w_kernel<<<(int)(((size_t)G4 * KTOT + 255) / 256), 256>>>(Wx, Wh);
    split_wattn_kernel<<<(int)(((size_t)G4 * H_ + 255) / 256), 256>>>(Wattn);
    split_at_kernel<<<(4096 * H_ + 255) / 256, 256>>>(A);
    prep_b_kernel<<<(G4 + 255) / 256, 256>>>(b);
    init_kernel<<<(N_ * H_ + 255) / 256, 256>>>(A);

    // PA = At @ Wattn_gi  (one-time, 3-pass bf16, fp32 out, coalesced layout)
    gemm3_kernel<0><<<dim3(G4 / BN_, 4096 / BM_), 256, GEMM_SMEM>>>(nullptr, 0);

    for (int t = 0; t < T_; t++) {
        score_kernel<<<N_, 256>>>(A);
        pac_kernel<<<N_ * 4, 256>>>();
        gemm3_kernel<1><<<dim3(G4 / BN_, N_ / BM_), 256, GEMM_SMEM>>>(out, t);
    }
}